// round 9
// baseline (speedup 1.0000x reference)
#include <cuda_runtime.h>
#include <cuda_fp16.h>
#include <cstdint>

#define HN 128
#define FF 256
#define NMAX 50048
#define EMAX 800000
#define EPS 1e-5f
#define NBLK_N (NMAX / 64)    // 782
#define NBLK_E (EMAX / 64)    // 12500

// ---------------- static scratch ----------------
__device__ float  g_P[(size_t)NMAX * FF];
__device__ __half g_h16[(size_t)EMAX * FF];
__device__ float  g_agg[(size_t)NMAX * HN];
__device__ uint4  g_Ae[(size_t)NBLK_E * 1024];   // edge A, fp16 frag-packed
__device__ uint4  g_An[(size_t)NBLK_N * 1024];   // node A, fp16 frag-packed
__device__ uint2  g_Wt16[2][2][4096];            // [mode][half] B fp16 frag-packed
__device__ float  g_stats1[2 * FF];
__device__ float  g_stats2[2 * HN];
__device__ float  g_scale[FF];
__device__ float  g_shift[FF];
__device__ int    g_is64;

// ---------------- helpers ----------------
__device__ __forceinline__ float sigmoidf_(float x) {
    return __fdividef(1.f, 1.f + __expf(-x));
}
__device__ __forceinline__ float tanhf_(float x) {
    float t = __expf(2.f * x);
    return 1.f - __fdividef(2.f, t + 1.f);
}
__device__ __forceinline__ void mma16(float* c, const uint4 a, const uint2 b) {
    asm volatile("mma.sync.aligned.m16n8k16.row.col.f32.f16.f16.f32 "
                 "{%0,%1,%2,%3},{%4,%5,%6,%7},{%8,%9},{%0,%1,%2,%3};"
                 : "+f"(c[0]), "+f"(c[1]), "+f"(c[2]), "+f"(c[3])
                 : "r"(a.x), "r"(a.y), "r"(a.z), "r"(a.w), "r"(b.x), "r"(b.y));
}
__device__ __forceinline__ uint32_t h2u(__half2 h) {
    return *reinterpret_cast<uint32_t*>(&h);
}

// ---------------- small kernels ----------------
__global__ void detect_kernel(const unsigned* __restrict__ u) {
    unsigned v = 0;
    for (int k = threadIdx.x; k < 64; k += 32) v |= u[2 * k + 1];
#pragma unroll
    for (int o = 16; o; o >>= 1) v |= __shfl_xor_sync(0xffffffffu, v, o);
    if (threadIdx.x == 0) g_is64 = (v == 0) ? 1 : 0;
}

__global__ void zero_kernel(int aggCount) {
    const int stride = gridDim.x * blockDim.x;
    const int t0 = blockIdx.x * blockDim.x + threadIdx.x;
    for (int j = t0; j < aggCount; j += stride) g_agg[j] = 0.f;
    if (t0 < 2 * FF) g_stats1[t0] = 0.f;
    if (t0 < 2 * HN) g_stats2[t0] = 0.f;
}

// A pack: unit gid = ((block*8 + ks)*4 + mt)*32 + lane -> one uint4 (a0..a3)
__global__ void prepA_kernel(const float* __restrict__ A, uint4* __restrict__ dst,
                             int M, int nunits) {
    const int gid = blockIdx.x * blockDim.x + threadIdx.x;
    if (gid >= nunits) return;
    const int lane = gid & 31, mt = (gid >> 5) & 3, ks = (gid >> 7) & 7;
    const int block = gid >> 10;
    const int r0 = block * 64 + mt * 16 + (lane >> 2);
    const int r1 = r0 + 8;
    const int c0 = ks * 16 + (lane & 3) * 2;
    float2 v00 = make_float2(0.f, 0.f), v01 = v00, v10 = v00, v11 = v00;
    if (r0 < M) {
        v00 = *(const float2*)(A + (size_t)r0 * HN + c0);
        v01 = *(const float2*)(A + (size_t)r0 * HN + c0 + 8);
    }
    if (r1 < M) {
        v10 = *(const float2*)(A + (size_t)r1 * HN + c0);
        v11 = *(const float2*)(A + (size_t)r1 * HN + c0 + 8);
    }
    uint4 o;
    o.x = h2u(__floats2half2_rn(v00.x, v00.y));
    o.y = h2u(__floats2half2_rn(v10.x, v10.y));
    o.z = h2u(__floats2half2_rn(v01.x, v01.y));
    o.w = h2u(__floats2half2_rn(v11.x, v11.y));
    dst[gid] = o;
}

// B pack (unchanged)
__global__ void prepW_kernel(const float* __restrict__ W1) {
    const int gid = blockIdx.x * blockDim.x + threadIdx.x;
    if (gid >= 16384) return;
    const int lane = gid & 31, nt = (gid >> 5) & 3, wn = (gid >> 7) & 3;
    const int ks = (gid >> 9) & 7, hf = (gid >> 12) & 1, mode = gid >> 13;
    const int n = hf * 128 + wn * 32 + nt * 8 + (lane >> 2);
    const int k = ks * 16 + (lane & 3) * 2 + mode * HN;
    uint2 o;
    o.x = h2u(__floats2half2_rn(W1[(size_t)k * FF + n], W1[(size_t)(k + 1) * FF + n]));
    o.y = h2u(__floats2half2_rn(W1[(size_t)(k + 8) * FF + n], W1[(size_t)(k + 9) * FF + n]));
    g_Wt16[mode][hf][gid & 4095] = o;
}

// ---------------- sync-free fp16 warp-mma GEMM, cross-job prefetch ----------
template <int MODE>
__global__ __launch_bounds__(256, 2) void mma_gemm(
    const uint4* __restrict__ Apk, const float* __restrict__ b1,
    const void* __restrict__ ibuf, void* __restrict__ outv, int M)
{
    __shared__ uint2 Bs[4096];
    __shared__ float sstat[256];

    const int tid = threadIdx.x, lane = tid & 31, wid = tid >> 5;
    const int wm = wid & 1, wn = wid >> 1;
    const int ntiles = (M + 127) >> 7;
    const long long njobs = (long long)ntiles * 2;
    const int G = gridDim.x;
    const int halfc = blockIdx.x & 1;
    const int is64 = (MODE == 1) ? g_is64 : 0;

    {   // B pack -> smem, once
        const uint4* src = (const uint4*)&g_Wt16[MODE][halfc][0];
        uint4* dstv = (uint4*)Bs;
        for (int i = tid; i < 2048; i += 256) dstv[i] = src[i];
    }
    if (MODE == 1) sstat[tid] = 0.f;
    __syncthreads();

    float acc[4][4][4];
#pragma unroll
    for (int mt = 0; mt < 4; mt++)
#pragma unroll
        for (int nt = 0; nt < 4; nt++)
#pragma unroll
            for (int r = 0; r < 4; r++) acc[mt][nt][r] = 0.f;

    long long job = blockIdx.x;
    if (job < njobs) {
        const uint4* abase = Apk + ((((job >> 1) << 1) + wm) << 10);
        uint4 acur[4];
#pragma unroll
        for (int mt = 0; mt < 4; mt++) acur[mt] = abase[mt * 32 + lane];

        while (true) {
            const long long tile = job >> 1;
            const long long rbase = tile << 7;
            const long long jobN = (job + G < njobs) ? (job + G) : job;
            const uint4* abaseN = Apk + ((((jobN >> 1) << 1) + wm) << 10);

            // prefetch edge indices for epilogue (MODE 1)
            int eidx[8];
            if (MODE == 1) {
#pragma unroll
                for (int mt = 0; mt < 4; mt++)
#pragma unroll
                    for (int h = 0; h < 2; h++) {
                        const long long row = rbase + wm * 64 + mt * 16 + (lane >> 2) + h * 8;
                        int v = 0;
                        if (row < (long long)M)
                            v = is64 ? (int)((const long long*)ibuf)[row]
                                     : ((const int*)ibuf)[row];
                        eidx[mt * 2 + h] = v;
                    }
            }

            // ---- mainloop: no barriers; last k-step prefetches next job ----
            uint4 anxt[4];
#pragma unroll
            for (int ks = 0; ks < 8; ks++) {
                uint2 bfr[4];
#pragma unroll
                for (int nt = 0; nt < 4; nt++)
                    bfr[nt] = Bs[(ks * 16 + wn * 4 + nt) * 32 + lane];
                if (ks < 7) {
#pragma unroll
                    for (int mt = 0; mt < 4; mt++)
                        anxt[mt] = abase[(ks + 1) * 128 + mt * 32 + lane];
                } else {
#pragma unroll
                    for (int mt = 0; mt < 4; mt++)
                        anxt[mt] = abaseN[mt * 32 + lane];
                }
#pragma unroll
                for (int mt = 0; mt < 4; mt++)
#pragma unroll
                    for (int nt = 0; nt < 4; nt++)
                        mma16(acc[mt][nt], acur[mt], bfr[nt]);
#pragma unroll
                for (int mt = 0; mt < 4; mt++) acur[mt] = anxt[mt];
            }

            // ---- epilogue ----
            float s[4][2], q[4][2];
            if (MODE == 1) {
#pragma unroll
                for (int nt = 0; nt < 4; nt++) {
                    s[nt][0] = s[nt][1] = 0.f; q[nt][0] = q[nt][1] = 0.f;
                }
            }
#pragma unroll
            for (int mt = 0; mt < 4; mt++) {
                bool valid[2]; long long rown[2]; long long pb[2];
#pragma unroll
                for (int h = 0; h < 2; h++) {
                    const long long row = rbase + wm * 64 + mt * 16 + (lane >> 2) + h * 8;
                    rown[h] = row;
                    valid[h] = row < (long long)M;
                    pb[h] = (MODE == 1) ? ((long long)eidx[mt * 2 + h] * FF) : 0;
                }
#pragma unroll
                for (int nt = 0; nt < 4; nt++) {
                    const int c0 = halfc * 128 + wn * 32 + nt * 8 + 2 * (lane & 3);
#pragma unroll
                    for (int h = 0; h < 2; h++) {
                        if (!valid[h]) continue;
                        float2 add;
                        if (MODE == 0) add = *(const float2*)(b1 + c0);
                        else           add = *(const float2*)(g_P + pb[h] + c0);
                        float2 o;
                        o.x = acc[mt][nt][2 * h] + add.x;
                        o.y = acc[mt][nt][2 * h + 1] + add.y;
                        if (MODE == 0) {
                            *(float2*)((float*)outv + rown[h] * FF + c0) = o;
                        } else {
                            *(__half2*)((__half*)outv + rown[h] * FF + c0) =
                                __floats2half2_rn(o.x, o.y);
                            s[nt][0] += o.x; q[nt][0] = fmaf(o.x, o.x, q[nt][0]);
                            s[nt][1] += o.y; q[nt][1] = fmaf(o.y, o.y, q[nt][1]);
                        }
                    }
                    acc[mt][nt][0] = 0.f; acc[mt][nt][1] = 0.f;
                    acc[mt][nt][2] = 0.f; acc[mt][nt][3] = 0.f;
                }
            }
            if (MODE == 1) {
#pragma unroll
                for (int o = 4; o < 32; o <<= 1) {
#pragma unroll
                    for (int nt = 0; nt < 4; nt++) {
                        s[nt][0] += __shfl_xor_sync(0xffffffffu, s[nt][0], o);
                        s[nt][1] += __shfl_xor_sync(0xffffffffu, s[nt][1], o);
                        q[nt][0] += __shfl_xor_sync(0xffffffffu, q[nt][0], o);
                        q[nt][1] += __shfl_xor_sync(0xffffffffu, q[nt][1], o);
                    }
                }
                if (lane < 4) {
#pragma unroll
                    for (int nt = 0; nt < 4; nt++) {
                        const int lc = wn * 32 + nt * 8 + 2 * lane;
                        atomicAdd(&sstat[lc], s[nt][0]);
                        atomicAdd(&sstat[lc + 1], s[nt][1]);
                        atomicAdd(&sstat[128 + lc], q[nt][0]);
                        atomicAdd(&sstat[128 + lc + 1], q[nt][1]);
                    }
                }
            }
            if (job + G >= njobs) break;
            job += G;
            abase = abaseN;
        }
    }
    if (MODE == 1) {
        __syncthreads();
        if (tid < 128) {
            atomicAdd(&g_stats1[halfc * 128 + tid], sstat[tid]);
            atomicAdd(&g_stats1[256 + halfc * 128 + tid], sstat[128 + tid]);
        }
    }
}

// ---------------- BN1 finalize ----------------
__global__ void finalize1_kernel(const float* __restrict__ gamma1,
                                 const float* __restrict__ beta1, float invE) {
    const int j = threadIdx.x;
    const float mu  = g_stats1[j] * invE;
    const float var = g_stats1[FF + j] * invE - mu * mu;
    const float s   = gamma1[j] * rsqrtf(var + EPS);
    g_scale[j] = s;
    g_shift[j] = beta1[j] - mu * s;
}

// ---------------- gate + scatter: 8 cols/thread ----------------
__global__ void gate_scatter_kernel(const void* __restrict__ ibuf, int E) {
    __shared__ float ssc[FF], ssh[FF];
    ssc[threadIdx.x] = g_scale[threadIdx.x];
    ssh[threadIdx.x] = g_shift[threadIdx.x];
    __syncthreads();
    const int is64 = g_is64;
    const long long total  = (long long)E * 16;
    const long long stride = (long long)gridDim.x * blockDim.x;
    for (long long t = (long long)blockIdx.x * blockDim.x + threadIdx.x;
         t < total; t += stride) {
        const long long e = t >> 4;
        const int c8 = (int)(t & 15) << 3;
        const __half* hrow = g_h16 + e * FF;
        const uint4 fv = *(const uint4*)(hrow + c8);        // 8 halves (filter)
        const uint4 gv = *(const uint4*)(hrow + HN + c8);   // 8 halves (core)
        const long long idx = is64 ? ((const long long*)ibuf)[e]
                                   : (long long)((const int*)ibuf)[e];
        float* dst = g_agg + idx * HN + c8;
        float m[8];
#pragma unroll
        for (int p = 0; p < 4; p++) {
            const float2 f2 = __half22float2(*(((const __half2*)&fv) + p));
            const float2 g2 = __half22float2(*(((const __half2*)&gv) + p));
            const int c = c8 + 2 * p;
            m[2 * p]     = sigmoidf_(f2.x * ssc[c]     + ssh[c])     * tanhf_(g2.x * ssc[HN + c]     + ssh[HN + c]);
            m[2 * p + 1] = sigmoidf_(f2.y * ssc[c + 1] + ssh[c + 1]) * tanhf_(g2.y * ssc[HN + c + 1] + ssh[HN + c + 1]);
        }
        asm volatile("red.global.add.v4.f32 [%0], {%1, %2, %3, %4};"
                     :: "l"(dst), "f"(m[0]), "f"(m[1]), "f"(m[2]), "f"(m[3]) : "memory");
        asm volatile("red.global.add.v4.f32 [%0], {%1, %2, %3, %4};"
                     :: "l"(dst + 4), "f"(m[4]), "f"(m[5]), "f"(m[6]), "f"(m[7]) : "memory");
    }
}

// ---------------- BN2 + final ----------------
__global__ void stats2_kernel(int N) {
    const int t = blockIdx.x * blockDim.x + threadIdx.x;
    const int col = t & (HN - 1);
    const int r0 = t >> 7;
    const int rs = (gridDim.x * blockDim.x) >> 7;
    float s = 0.f, sq = 0.f;
    for (long long r = r0; r < N; r += rs) {
        const float v = g_agg[r * HN + col];
        s += v; sq = fmaf(v, v, sq);
    }
    atomicAdd(&g_stats2[col], s);
    atomicAdd(&g_stats2[HN + col], sq);
}

__global__ void final_kernel(const float* __restrict__ node_emb,
                             const float* __restrict__ gamma2,
                             const float* __restrict__ beta2,
                             float* __restrict__ out, int total, float invN) {
    const int t = blockIdx.x * blockDim.x + threadIdx.x;
    if (t >= total) return;
    const int col = t & (HN - 1);
    const float mu  = g_stats2[col] * invN;
    const float var = g_stats2[HN + col] * invN - mu * mu;
    const float c1  = (g_agg[t] - mu) * rsqrtf(var + EPS) * gamma2[col] + beta2[col];
    out[t] = tanhf_(node_emb[t] + c1);
}

// ---------------- launch ----------------
extern "C" void kernel_launch(void* const* d_in, const int* in_sizes, int n_in,
                              void* d_out, int out_size) {
    const float* node_emb = (const float*)d_in[0];
    const float* edge_emb = (const float*)d_in[1];
    const void*  ibuf     = d_in[2];
    const float* W1       = (const float*)d_in[3];
    const float* b1       = (const float*)d_in[4];
    const float* gamma1   = (const float*)d_in[5];
    const float* beta1    = (const float*)d_in[6];
    const float* gamma2   = (const float*)d_in[7];
    const float* beta2    = (const float*)d_in[8];
    float* out = (float*)d_out;

    const int N = in_sizes[0] / HN;
    const int E = in_sizes[1] / HN;

    float*  g_P_ptr;  cudaGetSymbolAddress((void**)&g_P_ptr, g_P);
    __half* g_h_ptr;  cudaGetSymbolAddress((void**)&g_h_ptr, g_h16);
    uint4*  g_Ae_ptr; cudaGetSymbolAddress((void**)&g_Ae_ptr, g_Ae);
    uint4*  g_An_ptr; cudaGetSymbolAddress((void**)&g_An_ptr, g_An);

    detect_kernel<<<1, 32>>>((const unsigned*)ibuf);
    zero_kernel<<<4096, 256>>>(N * HN);
    prepW_kernel<<<64, 256>>>(W1);

    const int unitsN = NBLK_N * 1024;
    const int unitsE = NBLK_E * 1024;
    prepA_kernel<<<(unitsN + 255) / 256, 256>>>(node_emb, g_An_ptr, N, unitsN);
    prepA_kernel<<<(unitsE + 255) / 256, 256>>>(edge_emb, g_Ae_ptr, E, unitsE);

    mma_gemm<0><<<296, 256>>>(g_An_ptr, b1, ibuf, g_P_ptr, N);
    mma_gemm<1><<<296, 256>>>(g_Ae_ptr, b1, ibuf, g_h_ptr, E);

    finalize1_kernel<<<1, 256>>>(gamma1, beta1, 1.0f / (float)E);
    gate_scatter_kernel<<<8192, 256>>>(ibuf, E);

    stats2_kernel<<<1024, 256>>>(N);
    final_kernel<<<(N * HN + 255) / 256, 256>>>(node_emb, gamma2, beta2, out,
                                                N * HN, 1.0f / (float)N);
}